// round 4
// baseline (speedup 1.0000x reference)
#include <cuda_runtime.h>

#define MAXN 50000

// Scratch (device globals — referenced directly from device code; no
// allocation anywhere)
__device__ __align__(16) float g_dinv[MAXN];        // degree, then rsqrt(degree)
__device__ __align__(16) float g_buf1[MAXN * 128];  // A1, then A2
__device__ __align__(16) float g_buf2[MAXN * 128];  // T2

// ---------------------------------------------------------------------------
// Degree / normalization        (edge_index is int32: [2, E] row-major)
// ---------------------------------------------------------------------------
__global__ void k_init_deg(int n) {
    int i = blockIdx.x * blockDim.x + threadIdx.x;
    if (i < n) g_dinv[i] = 1.0f;  // self-loop
}

__global__ void k_count_deg(const int* __restrict__ ei, int E) {
    int i = blockIdx.x * blockDim.x + threadIdx.x;
    if (i < E) atomicAdd(&g_dinv[ei[E + i]], 1.0f);  // dst row
}

__global__ void k_dinv(int n) {
    int i = blockIdx.x * blockDim.x + threadIdx.x;
    if (i < n) g_dinv[i] = rsqrtf(g_dinv[i]);
}

// ---------------------------------------------------------------------------
// Aggregation: out = D^-1/2 (A+I) D^-1/2 * in   (feature dim = 128)
// pass 0: in = x (param), out = g_buf1
// pass 1: in = g_buf2,    out = g_buf1
// ---------------------------------------------------------------------------
__global__ void k_agg_init(const float* __restrict__ xin, int pass, int n) {
    int idx = blockIdx.x * blockDim.x + threadIdx.x;  // float4 units
    if (idx >= n * 32) return;
    const float* in = (pass == 0) ? xin : g_buf2;
    int i = idx >> 5;
    float s = g_dinv[i];
    s = s * s;
    float4 v = reinterpret_cast<const float4*>(in)[idx];
    v.x *= s; v.y *= s; v.z *= s; v.w *= s;
    reinterpret_cast<float4*>(g_buf1)[idx] = v;
}

// one warp per edge; 32 lanes x float4 = 128 floats
__global__ void __launch_bounds__(256) k_agg_edges(
    const float* __restrict__ xin, int pass,
    const int* __restrict__ ei, int E) {
    int gwarp = (blockIdx.x * blockDim.x + threadIdx.x) >> 5;
    int lane = threadIdx.x & 31;
    if (gwarp >= E) return;
    const float* in = (pass == 0) ? xin : g_buf2;
    int s = ei[gwarp];
    int d = ei[E + gwarp];
    float norm = g_dinv[s] * g_dinv[d];
    float4 v = reinterpret_cast<const float4*>(in + (size_t)s * 128)[lane];
    v.x *= norm; v.y *= norm; v.z *= norm; v.w *= norm;
    float4* p = reinterpret_cast<float4*>(g_buf1 + (size_t)d * 128) + lane;
    atomicAdd(p, v);   // sm_90+ vector reduction
}

// ---------------------------------------------------------------------------
// Fused: H1 = leaky(A1 @ W1 + b1) [16x512 in smem] ; T2 = H1 @ W3 [16x128]
// Block = 256 threads, BM = 16 nodes per block. All-static shared (40 KB).
// Reads g_buf1, writes g_buf2.
// ---------------------------------------------------------------------------
__global__ void __launch_bounds__(256) k_gemm12(
    const float* __restrict__ W1, const float* __restrict__ b1,
    const float* __restrict__ W3, int n) {
    __shared__ float a1s[16][128];   // 8 KB
    __shared__ float h1s[16][512];   // 32 KB

    int tid = threadIdx.x;
    int base = blockIdx.x * 16;
    int valid = n - base;
    if (valid > 16) valid = 16;

    // Load A1 tile (zero-pad invalid rows): 16 rows x 32 float4
    for (int idx = tid; idx < 16 * 32; idx += 256) {
        int m = idx >> 5, c = idx & 31;
        float4 v = make_float4(0.f, 0.f, 0.f, 0.f);
        if (m < valid)
            v = reinterpret_cast<const float4*>(g_buf1 + (size_t)(base + m) * 128)[c];
        reinterpret_cast<float4*>(&a1s[m][0])[c] = v;
    }
    __syncthreads();

    // Phase 1: thread tid -> H1 columns (tid, tid+256), all 16 rows
    {
        int j = tid;
        float acc0[16], acc1[16];
#pragma unroll
        for (int m = 0; m < 16; m++) { acc0[m] = 0.f; acc1[m] = 0.f; }

        for (int k4 = 0; k4 < 32; k4++) {
            float w0[4], w1v[4];
#pragma unroll
            for (int i = 0; i < 4; i++) {
                w0[i]  = W1[(size_t)(k4 * 4 + i) * 512 + j];
                w1v[i] = W1[(size_t)(k4 * 4 + i) * 512 + j + 256];
            }
#pragma unroll
            for (int m = 0; m < 16; m++) {
                float4 a = reinterpret_cast<const float4*>(&a1s[m][0])[k4];
                acc0[m] += a.x * w0[0];  acc0[m] += a.y * w0[1];
                acc0[m] += a.z * w0[2];  acc0[m] += a.w * w0[3];
                acc1[m] += a.x * w1v[0]; acc1[m] += a.y * w1v[1];
                acc1[m] += a.z * w1v[2]; acc1[m] += a.w * w1v[3];
            }
        }
        float bb0 = b1[j], bb1 = b1[j + 256];
#pragma unroll
        for (int m = 0; m < 16; m++) {
            float v0 = acc0[m] + bb0;
            float v1 = acc1[m] + bb1;
            h1s[m][j]       = (v0 >= 0.f) ? v0 : 0.01f * v0;
            h1s[m][j + 256] = (v1 >= 0.f) ? v1 : 0.01f * v1;
        }
    }
    __syncthreads();

    // Phase 2: T2 = H1 @ W3. thread -> col jc = tid&127, 8 rows
    {
        int jc = tid & 127;
        int mb = (tid >> 7) * 8;
        float acc[8];
#pragma unroll
        for (int m = 0; m < 8; m++) acc[m] = 0.f;

        for (int k4 = 0; k4 < 128; k4++) {
            float w[4];
#pragma unroll
            for (int i = 0; i < 4; i++)
                w[i] = W3[(size_t)(k4 * 4 + i) * 128 + jc];
#pragma unroll
            for (int m = 0; m < 8; m++) {
                float4 h = reinterpret_cast<const float4*>(&h1s[mb + m][0])[k4];
                acc[m] += h.x * w[0]; acc[m] += h.y * w[1];
                acc[m] += h.z * w[2]; acc[m] += h.w * w[3];
            }
        }
#pragma unroll
        for (int m = 0; m < 8; m++) {
            if (mb + m < valid)
                g_buf2[(size_t)(base + mb + m) * 128 + jc] = acc[m];
        }
    }
}

// ---------------------------------------------------------------------------
// Final: h2 = leaky(A2 + b3); h3 = leaky(h2 @ fc1_w^T + fc1_b);
//        out = h3 @ fc2_w^T + fc2_b        (reads g_buf1)
// Block = 256 threads (one per FC1 output channel), 32 nodes per block.
// ---------------------------------------------------------------------------
__global__ void __launch_bounds__(256) k_final(
    const float* __restrict__ b3,
    const float* __restrict__ fc1w, const float* __restrict__ fc1b,
    const float* __restrict__ fc2w, const float* __restrict__ fc2b,
    float* __restrict__ out, int n) {
    __shared__ float h2s[32][128];   // 16 KB
    __shared__ float red[32][8];

    int tid = threadIdx.x;
    int base = blockIdx.x * 32;
    int valid = n - base;
    if (valid > 32) valid = 32;

    for (int idx = tid; idx < 32 * 32; idx += 256) {
        int m = idx >> 5, c = idx & 31;
        float4 v = make_float4(0.f, 0.f, 0.f, 0.f);
        if (m < valid)
            v = reinterpret_cast<const float4*>(g_buf1 + (size_t)(base + m) * 128)[c];
        float4 bb = reinterpret_cast<const float4*>(b3)[c];
        v.x += bb.x; v.y += bb.y; v.z += bb.z; v.w += bb.w;
        v.x = (v.x >= 0.f) ? v.x : 0.01f * v.x;
        v.y = (v.y >= 0.f) ? v.y : 0.01f * v.y;
        v.z = (v.z >= 0.f) ? v.z : 0.01f * v.z;
        v.w = (v.w >= 0.f) ? v.w : 0.01f * v.w;
        reinterpret_cast<float4*>(&h2s[m][0])[c] = v;
    }
    __syncthreads();

    int j = tid;  // FC1 output channel
    float acc[32];
#pragma unroll
    for (int m = 0; m < 32; m++) acc[m] = 0.f;

    for (int k4 = 0; k4 < 32; k4++) {
        float4 w = reinterpret_cast<const float4*>(fc1w + (size_t)j * 128)[k4];
#pragma unroll
        for (int m = 0; m < 32; m++) {
            float4 h = reinterpret_cast<const float4*>(&h2s[m][0])[k4];
            acc[m] += h.x * w.x; acc[m] += h.y * w.y;
            acc[m] += h.z * w.z; acc[m] += h.w * w.w;
        }
    }

    float fb = fc1b[j], w2 = fc2w[j];
    int lane = tid & 31, wid = tid >> 5;
#pragma unroll
    for (int m = 0; m < 32; m++) {
        float v = acc[m] + fb;
        v = (v >= 0.f) ? v : 0.01f * v;
        v *= w2;
#pragma unroll
        for (int off = 16; off; off >>= 1)
            v += __shfl_xor_sync(0xffffffffu, v, off);
        if (lane == 0) red[m][wid] = v;
    }
    __syncthreads();

    if (tid < 32 && tid < valid) {
        float s = fc2b[0];
#pragma unroll
        for (int w = 0; w < 8; w++) s += red[tid][w];
        out[base + tid] = s;
    }
}

// ---------------------------------------------------------------------------
extern "C" void kernel_launch(void* const* d_in, const int* in_sizes, int n_in,
                              void* d_out, int out_size) {
    const float* x    = (const float*)d_in[0];
    const int*   ei   = (const int*)d_in[1];      // int32! (JAX x64 disabled)
    const float* W1   = (const float*)d_in[2];
    const float* b1   = (const float*)d_in[3];
    const float* W3   = (const float*)d_in[4];
    const float* b3   = (const float*)d_in[5];
    const float* fc1w = (const float*)d_in[6];
    const float* fc1b = (const float*)d_in[7];
    const float* fc2w = (const float*)d_in[8];
    const float* fc2b = (const float*)d_in[9];
    float* out = (float*)d_out;

    int n = in_sizes[0] / 128;
    int E = in_sizes[1] / 2;

    // 1) degree / dinv
    int nb = (n + 255) / 256;
    k_init_deg<<<nb, 256>>>(n);
    k_count_deg<<<(E + 255) / 256, 256>>>(ei, E);
    k_dinv<<<nb, 256>>>(n);

    // 2) A1 = Ahat @ x   -> g_buf1
    k_agg_init<<<(n * 32 + 255) / 256, 256>>>(x, 0, n);
    k_agg_edges<<<(E * 32 + 255) / 256, 256>>>(x, 0, ei, E);

    // 3) T2 = leaky(A1@W1+b1) @ W3   -> g_buf2
    k_gemm12<<<(n + 15) / 16, 256>>>(W1, b1, W3, n);

    // 4) A2 = Ahat @ T2   -> g_buf1
    k_agg_init<<<(n * 32 + 255) / 256, 256>>>(x, 1, n);
    k_agg_edges<<<(E * 32 + 255) / 256, 256>>>(x, 1, ei, E);

    // 5) head
    k_final<<<(n + 31) / 32, 256>>>(b3, fc1w, fc1b, fc2w, fc2b, out, n);
}